// round 4
// baseline (speedup 1.0000x reference)
#include <cuda_runtime.h>

// MedianPool2d 3x3, stride 1, reflect pad (1,1,1,1)
// float32 [16, 3, 512, 512] -> same shape.
//
// 4(W) x 4(H) outputs per thread, phased (as R3). NEW: the vertical sorting
// stage (row-pair sorts + merge of third row) runs on the FMA pipe via packed
// f32x2 arithmetic compare-exchange:
//     lo = 0.5*(a+b) - 0.5*|a-b|,  hi = 0.5*(a+b) + 0.5*|a-b|
// processing two column-pairs per instruction. This moves ~60 of the ~140
// min/max pairs per tile off the saturated ALU pipe (FMNMX) onto the idle
// FMA pipe. Horizontal combine stays scalar FMNMX.
//
// Column packing per row: lane A = (c1,c2), lane B = (c3,c4)  [free: float4
// halves], lane C = (c0,c5) [the two reflected halo scalars].

#define W 512
#define H 512

typedef unsigned long long u64;

__device__ __forceinline__ u64 pk(float x, float y) {
    u64 r; asm("mov.b64 %0, {%1, %2};" : "=l"(r) : "f"(x), "f"(y)); return r;
}
__device__ __forceinline__ float2 upk(u64 v) {
    float2 f; asm("mov.b64 {%0, %1}, %2;" : "=f"(f.x), "=f"(f.y) : "l"(v)); return f;
}

// packed compare-exchange on 2 fp32 lanes: lo=min, hi=max (within ~1 ulp)
__device__ __forceinline__ void cex2(u64 a, u64 b, u64& lo, u64& hi,
                                     u64 negone2, u64 half2, u64 neghalf2) {
    u64 s, d, k, h;
    asm("add.rn.f32x2 %0, %1, %2;" : "=l"(s) : "l"(a), "l"(b));
    asm("fma.rn.f32x2 %0, %1, %2, %3;" : "=l"(d) : "l"(b), "l"(negone2), "l"(a)); // a-b
    k = d & 0x7FFFFFFF7FFFFFFFULL;                                                // |a-b|
    asm("mul.rn.f32x2 %0, %1, %2;" : "=l"(h) : "l"(s), "l"(half2));               // 0.5(a+b)
    asm("fma.rn.f32x2 %0, %1, %2, %3;" : "=l"(lo) : "l"(k), "l"(neghalf2), "l"(h));
    asm("fma.rn.f32x2 %0, %1, %2, %3;" : "=l"(hi) : "l"(k), "l"(half2), "l"(h));
}

__device__ __forceinline__ float med3(float a, float b, float c) {
    return fmaxf(fminf(a, b), fminf(fmaxf(a, b), c));
}

struct Row3 { u64 a, b, c; };   // packed columns (1,2) (3,4) (0,5)

__device__ __forceinline__ Row3 load_row(const float* __restrict__ row,
                                         int w0, int wl, int wr) {
    float4 q = *reinterpret_cast<const float4*>(row + w0);
    Row3 r;
    r.a = pk(q.x, q.y);
    r.b = pk(q.z, q.w);
    r.c = pk(row[wl], row[wr]);
    return r;
}

// vertical pair sort of two rows (packed, fma pipe)
__device__ __forceinline__ void pair_sort(const Row3& x, const Row3& y,
                                          Row3& pl, Row3& ph,
                                          u64 n1, u64 hf, u64 nh) {
    cex2(x.a, y.a, pl.a, ph.a, n1, hf, nh);
    cex2(x.b, y.b, pl.b, ph.b, n1, hf, nh);
    cex2(x.c, y.c, pl.c, ph.c, n1, hf, nh);
}

// merge third row into sorted pair (packed, fma pipe), then horizontal
// combine (scalar, alu pipe), store 4 outputs.
__device__ __forceinline__ void emit_row(const Row3& pl, const Row3& ph,
                                         const Row3& t,
                                         u64 n1, u64 hf, u64 nh,
                                         float* __restrict__ dst) {
    Row3 lo, mi, hi, tm;
    cex2(pl.a, t.a, lo.a, tm.a, n1, hf, nh);
    cex2(ph.a, tm.a, mi.a, hi.a, n1, hf, nh);
    cex2(pl.b, t.b, lo.b, tm.b, n1, hf, nh);
    cex2(ph.b, tm.b, mi.b, hi.b, n1, hf, nh);
    cex2(pl.c, t.c, lo.c, tm.c, n1, hf, nh);
    cex2(ph.c, tm.c, mi.c, hi.c, n1, hf, nh);

    float2 la = upk(lo.a), lb = upk(lo.b), lc = upk(lo.c);
    float2 ma = upk(mi.a), mb = upk(mi.b), mc = upk(mi.c);
    float2 ha = upk(hi.a), hb = upk(hi.b), hc = upk(hi.c);
    // columns: 0=*.c.x  1=*.a.x  2=*.a.y  3=*.b.x  4=*.b.y  5=*.c.y

    // max-of-3 lows (shared middle pairs)
    float sA = fmaxf(la.x, la.y);
    float sB = fmaxf(lb.x, lb.y);
    float mlo0 = fmaxf(lc.x, sA);
    float mlo1 = fmaxf(sA, lb.x);
    float mlo2 = fmaxf(la.y, sB);
    float mlo3 = fmaxf(sB, lc.y);

    // min-of-3 highs
    float tA = fminf(ha.x, ha.y);
    float tB = fminf(hb.x, hb.y);
    float mhi0 = fminf(hc.x, tA);
    float mhi1 = fminf(tA, hb.x);
    float mhi2 = fminf(ha.y, tB);
    float mhi3 = fminf(tB, hc.y);

    // med3 of mids with shared sorted pairs
    float q0A = fminf(ma.x, ma.y), q1A = fmaxf(ma.x, ma.y);
    float q0B = fminf(mb.x, mb.y), q1B = fmaxf(mb.x, mb.y);
    float mmi0 = fmaxf(q0A, fminf(q1A, mc.x));
    float mmi1 = fmaxf(q0A, fminf(q1A, mb.x));
    float mmi2 = fmaxf(q0B, fminf(q1B, ma.y));
    float mmi3 = fmaxf(q0B, fminf(q1B, mc.y));

    float4 res;
    res.x = med3(mlo0, mmi0, mhi0);
    res.y = med3(mlo1, mmi1, mhi1);
    res.z = med3(mlo2, mmi2, mhi2);
    res.w = med3(mlo3, mmi3, mhi3);
    *reinterpret_cast<float4*>(dst) = res;
}

__global__ __launch_bounds__(128, 9)
void median3x3_kernel(const float* __restrict__ x, float* __restrict__ out) {
    const int tid   = threadIdx.x;       // 0..127
    const int h0    = blockIdx.x << 2;   // 4 output rows per block
    const int plane = blockIdx.y;        // 0..47
    const int w0    = tid << 2;

    const u64 n1 = 0xBF800000BF800000ULL;   // (-1, -1)
    const u64 hf = 0x3F0000003F000000ULL;   // (0.5, 0.5)
    const u64 nh = 0xBF000000BF000000ULL;   // (-0.5, -0.5)

    const long base = (long)plane * (H * W);
    const float* p = x + base;

    const int wl = (w0 == 0)     ? 1     : w0 - 1;
    const int wr = (w0 + 4 == W) ? W - 2 : w0 + 4;

    const int hf0 = (h0 == 0) ? 1 : h0 - 1;
    const int hf5 = (h0 + 4 >= H) ? H - 2 : h0 + 4;

    // ---- phase A: frame rows f0..f3 ----
    Row3 f0 = load_row(p + (long)hf0      * W, w0, wl, wr);
    Row3 f1 = load_row(p + (long)h0       * W, w0, wl, wr);
    Row3 f2 = load_row(p + (long)(h0 + 1) * W, w0, wl, wr);
    Row3 f3 = load_row(p + (long)(h0 + 2) * W, w0, wl, wr);

    Row3 pAl, pAh;
    pair_sort(f1, f2, pAl, pAh, n1, hf, nh);   // f1 dead (never a third)

    float* o = out + base + (long)h0 * W + w0;
    emit_row(pAl, pAh, f0, n1, hf, nh, o);          // row 0 ; f0 dies
    emit_row(pAl, pAh, f3, n1, hf, nh, o + W);      // row 1 ; pairA dies

    // ---- phase B: frame rows f4, f5 ----
    Row3 f4 = load_row(p + (long)(h0 + 3) * W, w0, wl, wr);
    Row3 f5 = load_row(p + (long)hf5      * W, w0, wl, wr);

    Row3 pBl, pBh;
    pair_sort(f3, f4, pBl, pBh, n1, hf, nh);   // f3, f4 dead

    emit_row(pBl, pBh, f2, n1, hf, nh, o + 2 * W);  // row 2 ; f2 dies
    emit_row(pBl, pBh, f5, n1, hf, nh, o + 3 * W);  // row 3
}

extern "C" void kernel_launch(void* const* d_in, const int* in_sizes, int n_in,
                              void* d_out, int out_size) {
    const float* x = (const float*)d_in[0];
    float* out = (float*)d_out;
    dim3 grid(H / 4, 48);
    dim3 block(128);
    median3x3_kernel<<<grid, block>>>(x, out);
}

// round 5
// speedup vs baseline: 1.0107x; 1.0107x over previous
#include <cuda_runtime.h>

// MedianPool2d 3x3, stride 1, reflect pad (1,1,1,1)
// float32 [16, 3, 512, 512] -> same shape.
//
// 4(W) x 2(H) outputs per thread. Vertical stage (pair sort + third-row merge)
// on the FMA pipe via packed f32x2 arithmetic compare-exchange; horizontal
// combine scalar FMNMX (ALU pipe). Small tile -> low register pressure ->
// higher occupancy; all loads batched up front for MLP.
//
// Column packing per row: lane A=(c1,c2), lane B=(c3,c4) [float4 halves],
// lane C=(c0,c5) [reflected halo scalars].

#define W 512
#define H 512

typedef unsigned long long u64;

__device__ __forceinline__ u64 pk(float x, float y) {
    u64 r; asm("mov.b64 %0, {%1, %2};" : "=l"(r) : "f"(x), "f"(y)); return r;
}
__device__ __forceinline__ float2 upk(u64 v) {
    float2 f; asm("mov.b64 {%0, %1}, %2;" : "=f"(f.x), "=f"(f.y) : "l"(v)); return f;
}

// packed compare-exchange on 2 fp32 lanes: lo=min, hi=max
__device__ __forceinline__ void cex2(u64 a, u64 b, u64& lo, u64& hi,
                                     u64 negone2, u64 half2, u64 neghalf2) {
    u64 s, d, k, h;
    asm("add.rn.f32x2 %0, %1, %2;" : "=l"(s) : "l"(a), "l"(b));
    asm("fma.rn.f32x2 %0, %1, %2, %3;" : "=l"(d) : "l"(b), "l"(negone2), "l"(a)); // a-b
    k = d & 0x7FFFFFFF7FFFFFFFULL;                                                // |a-b|
    asm("mul.rn.f32x2 %0, %1, %2;" : "=l"(h) : "l"(s), "l"(half2));               // 0.5(a+b)
    asm("fma.rn.f32x2 %0, %1, %2, %3;" : "=l"(lo) : "l"(k), "l"(neghalf2), "l"(h));
    asm("fma.rn.f32x2 %0, %1, %2, %3;" : "=l"(hi) : "l"(k), "l"(half2), "l"(h));
}

__device__ __forceinline__ float med3(float a, float b, float c) {
    return fmaxf(fminf(a, b), fminf(fmaxf(a, b), c));
}

struct Row3 { u64 a, b, c; };

__device__ __forceinline__ Row3 pack_row(float4 q, float l, float r) {
    Row3 rr;
    rr.a = pk(q.x, q.y);
    rr.b = pk(q.z, q.w);
    rr.c = pk(l, r);
    return rr;
}

// merge third row into sorted pair (packed, fma pipe), then horizontal
// combine (scalar FMNMX, alu pipe), store 4 outputs.
__device__ __forceinline__ void emit_row(const Row3& pl, const Row3& ph,
                                         const Row3& t,
                                         u64 n1, u64 hf, u64 nh,
                                         float* __restrict__ dst) {
    Row3 lo, mi, hi, tm;
    cex2(pl.a, t.a, lo.a, tm.a, n1, hf, nh);
    cex2(ph.a, tm.a, mi.a, hi.a, n1, hf, nh);
    cex2(pl.b, t.b, lo.b, tm.b, n1, hf, nh);
    cex2(ph.b, tm.b, mi.b, hi.b, n1, hf, nh);
    cex2(pl.c, t.c, lo.c, tm.c, n1, hf, nh);
    cex2(ph.c, tm.c, mi.c, hi.c, n1, hf, nh);

    float2 la = upk(lo.a), lb = upk(lo.b), lc = upk(lo.c);
    float2 ma = upk(mi.a), mb = upk(mi.b), mc = upk(mi.c);
    float2 ha = upk(hi.a), hb = upk(hi.b), hc = upk(hi.c);
    // columns: 0=*.c.x  1=*.a.x  2=*.a.y  3=*.b.x  4=*.b.y  5=*.c.y

    float sA = fmaxf(la.x, la.y);
    float sB = fmaxf(lb.x, lb.y);
    float mlo0 = fmaxf(lc.x, sA);
    float mlo1 = fmaxf(sA, lb.x);
    float mlo2 = fmaxf(la.y, sB);
    float mlo3 = fmaxf(sB, lc.y);

    float tA = fminf(ha.x, ha.y);
    float tB = fminf(hb.x, hb.y);
    float mhi0 = fminf(hc.x, tA);
    float mhi1 = fminf(tA, hb.x);
    float mhi2 = fminf(ha.y, tB);
    float mhi3 = fminf(tB, hc.y);

    float q0A = fminf(ma.x, ma.y), q1A = fmaxf(ma.x, ma.y);
    float q0B = fminf(mb.x, mb.y), q1B = fmaxf(mb.x, mb.y);
    float mmi0 = fmaxf(q0A, fminf(q1A, mc.x));
    float mmi1 = fmaxf(q0A, fminf(q1A, mb.x));
    float mmi2 = fmaxf(q0B, fminf(q1B, ma.y));
    float mmi3 = fmaxf(q0B, fminf(q1B, mc.y));

    float4 res;
    res.x = med3(mlo0, mmi0, mhi0);
    res.y = med3(mlo1, mmi1, mhi1);
    res.z = med3(mlo2, mmi2, mhi2);
    res.w = med3(mlo3, mmi3, mhi3);
    *reinterpret_cast<float4*>(dst) = res;
}

__global__ __launch_bounds__(128, 10)
void median3x3_kernel(const float* __restrict__ x, float* __restrict__ out) {
    const int tid   = threadIdx.x;        // 0..127
    const int h0    = blockIdx.x << 1;    // 2 output rows per block
    const int plane = blockIdx.y;         // 0..47
    const int w0    = tid << 2;

    const u64 n1 = 0xBF800000BF800000ULL;   // (-1, -1)
    const u64 hf = 0x3F0000003F000000ULL;   // (0.5, 0.5)
    const u64 nh = 0xBF000000BF000000ULL;   // (-0.5, -0.5)

    const long base = (long)plane * (H * W);
    const float* p = x + base;

    const int wl = (w0 == 0)     ? 1     : w0 - 1;
    const int wr = (w0 + 4 == W) ? W - 2 : w0 + 4;

    // frame rows f0..f3 = input rows h0-1 .. h0+2 (reflected at edges)
    const int hr0 = (h0 == 0)      ? 1     : h0 - 1;
    const int hr3 = (h0 + 2 >= H)  ? H - 2 : h0 + 2;

    const float* r0 = p + (long)hr0      * W;
    const float* r1 = p + (long)h0       * W;
    const float* r2 = p + (long)(h0 + 1) * W;
    const float* r3 = p + (long)hr3      * W;

    // batch ALL loads up front (12 LDGs in flight)
    float4 q0 = *reinterpret_cast<const float4*>(r0 + w0);
    float4 q1 = *reinterpret_cast<const float4*>(r1 + w0);
    float4 q2 = *reinterpret_cast<const float4*>(r2 + w0);
    float4 q3 = *reinterpret_cast<const float4*>(r3 + w0);
    float l0 = r0[wl], e0 = r0[wr];
    float l1 = r1[wl], e1 = r1[wr];
    float l2 = r2[wl], e2 = r2[wr];
    float l3 = r3[wl], e3 = r3[wr];

    Row3 f0 = pack_row(q0, l0, e0);
    Row3 f1 = pack_row(q1, l1, e1);
    Row3 f2 = pack_row(q2, l2, e2);
    Row3 f3 = pack_row(q3, l3, e3);

    // pair sort rows f1,f2 (both die afterward)
    Row3 pl, ph;
    cex2(f1.a, f2.a, pl.a, ph.a, n1, hf, nh);
    cex2(f1.b, f2.b, pl.b, ph.b, n1, hf, nh);
    cex2(f1.c, f2.c, pl.c, ph.c, n1, hf, nh);

    float* o = out + base + (long)h0 * W + w0;
    emit_row(pl, ph, f0, n1, hf, nh, o);        // output row h0
    emit_row(pl, ph, f3, n1, hf, nh, o + W);    // output row h0+1
}

extern "C" void kernel_launch(void* const* d_in, const int* in_sizes, int n_in,
                              void* d_out, int out_size) {
    const float* x = (const float*)d_in[0];
    float* out = (float*)d_out;
    dim3 grid(H / 2, 48);    // 256 row-pairs x 48 planes
    dim3 block(128);
    median3x3_kernel<<<grid, block>>>(x, out);
}

// round 6
// speedup vs baseline: 1.0122x; 1.0015x over previous
#include <cuda_runtime.h>

// MedianPool2d 3x3, stride 1, reflect pad (1,1,1,1)
// float32 [16, 3, 512, 512] -> same shape.
//
// 4(W) x 2(H) outputs per thread. Vertical stage (pair sort + third-row merge)
// on the FMA pipe via packed f32x2 arithmetic compare-exchange; horizontal
// combine scalar FMNMX (ALU pipe).
// R6: 32-bit offset addressing + split half-combines to cut register pressure;
// __launch_bounds__(128,12) raises the occupancy ceiling to 75%.

#define W 512
#define H 512

typedef unsigned long long u64;
typedef unsigned int u32;

__device__ __forceinline__ u64 pk(float x, float y) {
    u64 r; asm("mov.b64 %0, {%1, %2};" : "=l"(r) : "f"(x), "f"(y)); return r;
}
__device__ __forceinline__ float2 upk(u64 v) {
    float2 f; asm("mov.b64 {%0, %1}, %2;" : "=f"(f.x), "=f"(f.y) : "l"(v)); return f;
}

// packed compare-exchange on 2 fp32 lanes: lo=min, hi=max
__device__ __forceinline__ void cex2(u64 a, u64 b, u64& lo, u64& hi) {
    const u64 n1 = 0xBF800000BF800000ULL;   // (-1,-1)
    const u64 hf = 0x3F0000003F000000ULL;   // (0.5,0.5)
    const u64 nh = 0xBF000000BF000000ULL;   // (-0.5,-0.5)
    u64 s, d, k, h;
    asm("add.rn.f32x2 %0, %1, %2;" : "=l"(s) : "l"(a), "l"(b));
    asm("fma.rn.f32x2 %0, %1, %2, %3;" : "=l"(d) : "l"(b), "l"(n1), "l"(a)); // a-b
    k = d & 0x7FFFFFFF7FFFFFFFULL;                                           // |a-b|
    asm("mul.rn.f32x2 %0, %1, %2;" : "=l"(h) : "l"(s), "l"(hf));             // 0.5(a+b)
    asm("fma.rn.f32x2 %0, %1, %2, %3;" : "=l"(lo) : "l"(k), "l"(nh), "l"(h));
    asm("fma.rn.f32x2 %0, %1, %2, %3;" : "=l"(hi) : "l"(k), "l"(hf), "l"(h));
}

__device__ __forceinline__ float med3(float a, float b, float c) {
    return fmaxf(fminf(a, b), fminf(fmaxf(a, b), c));
}

struct Row3 { u64 a, b, c; };   // packed columns (1,2) (3,4) (0,5)

// merge third row into sorted pair and do the horizontal combine in two
// halves (groups a+c -> outputs 0,1 ; group b -> outputs 2,3) to keep
// register pressure low.
__device__ __forceinline__ void emit_row(const Row3& pl, const Row3& ph,
                                         const Row3& t,
                                         float* __restrict__ dst) {
    float4 res;
    // ---- half 1: groups a (cols 1,2) and c (cols 0,5) ----
    u64 loa, mia, hia, loc, mic, hic, tm;
    cex2(pl.a, t.a, loa, tm);
    cex2(ph.a, tm, mia, hia);
    cex2(pl.c, t.c, loc, tm);
    cex2(ph.c, tm, mic, hic);

    float2 la = upk(loa), lc = upk(loc);
    float2 ma = upk(mia), mc = upk(mic);
    float2 ha = upk(hia), hc = upk(hic);

    float sA  = fmaxf(la.x, la.y);            // max(lo1,lo2)
    float tA  = fminf(ha.x, ha.y);            // min(hi1,hi2)
    float q0A = fminf(ma.x, ma.y), q1A = fmaxf(ma.x, ma.y);

    // ---- half 2: group b (cols 3,4) ----
    u64 lob, mib, hib;
    cex2(pl.b, t.b, lob, tm);
    cex2(ph.b, tm, mib, hib);
    float2 lb = upk(lob), mb = upk(mib), hb = upk(hib);

    // outputs 0,1 (need groups a,c + lo3/hi3/mi3 = lb.x/hb.x/mb.x)
    res.x = med3(fmaxf(lc.x, sA),
                 fmaxf(q0A, fminf(q1A, mc.x)),
                 fminf(hc.x, tA));
    res.y = med3(fmaxf(sA, lb.x),
                 fmaxf(q0A, fminf(q1A, mb.x)),
                 fminf(tA, hb.x));

    float sB  = fmaxf(lb.x, lb.y);
    float tB  = fminf(hb.x, hb.y);
    float q0B = fminf(mb.x, mb.y), q1B = fmaxf(mb.x, mb.y);

    res.z = med3(fmaxf(la.y, sB),
                 fmaxf(q0B, fminf(q1B, ma.y)),
                 fminf(ha.y, tB));
    res.w = med3(fmaxf(sB, lc.y),
                 fmaxf(q0B, fminf(q1B, mc.y)),
                 fminf(tB, hc.y));

    *reinterpret_cast<float4*>(dst) = res;
}

__global__ __launch_bounds__(128, 12)
void median3x3_kernel(const float* __restrict__ x, float* __restrict__ out) {
    const int tid   = threadIdx.x;        // 0..127
    const int h0    = blockIdx.x << 1;    // 2 output rows per block
    const u32 plane = blockIdx.y;         // 0..47
    const int w0    = tid << 2;

    const u32 base = plane * (u32)(H * W);

    const int wl = (w0 == 0)     ? 1     : w0 - 1;
    const int wr = (w0 + 4 == W) ? W - 2 : w0 + 4;

    // frame rows f0..f3 = input rows h0-1 .. h0+2 (reflected at edges)
    const int hr0 = (h0 == 0)     ? 1     : h0 - 1;
    const int hr3 = (h0 + 2 >= H) ? H - 2 : h0 + 2;

    const u32 o0 = base + (u32)hr0 * W;
    const u32 o1 = base + (u32)h0  * W;
    const u32 o2 = o1 + W;
    const u32 o3 = base + (u32)hr3 * W;

    // batch ALL loads up front (12 LDGs in flight)
    float4 q0 = *reinterpret_cast<const float4*>(x + o0 + w0);
    float4 q1 = *reinterpret_cast<const float4*>(x + o1 + w0);
    float4 q2 = *reinterpret_cast<const float4*>(x + o2 + w0);
    float4 q3 = *reinterpret_cast<const float4*>(x + o3 + w0);
    float l0 = x[o0 + wl], e0 = x[o0 + wr];
    float l1 = x[o1 + wl], e1 = x[o1 + wr];
    float l2 = x[o2 + wl], e2 = x[o2 + wr];
    float l3 = x[o3 + wl], e3 = x[o3 + wr];

    Row3 f0, f1, f2, f3;
    f0.a = pk(q0.x, q0.y); f0.b = pk(q0.z, q0.w); f0.c = pk(l0, e0);
    f1.a = pk(q1.x, q1.y); f1.b = pk(q1.z, q1.w); f1.c = pk(l1, e1);
    f2.a = pk(q2.x, q2.y); f2.b = pk(q2.z, q2.w); f2.c = pk(l2, e2);
    f3.a = pk(q3.x, q3.y); f3.b = pk(q3.z, q3.w); f3.c = pk(l3, e3);

    // pair sort rows f1,f2 (both die afterward)
    Row3 pl, ph;
    cex2(f1.a, f2.a, pl.a, ph.a);
    cex2(f1.b, f2.b, pl.b, ph.b);
    cex2(f1.c, f2.c, pl.c, ph.c);

    float* o = out + o1 + w0;
    emit_row(pl, ph, f0, o);        // output row h0
    emit_row(pl, ph, f3, o + W);    // output row h0+1
}

extern "C" void kernel_launch(void* const* d_in, const int* in_sizes, int n_in,
                              void* d_out, int out_size) {
    const float* x = (const float*)d_in[0];
    float* out = (float*)d_out;
    dim3 grid(H / 2, 48);    // 256 row-pairs x 48 planes
    dim3 block(128);
    median3x3_kernel<<<grid, block>>>(x, out);
}

// round 7
// speedup vs baseline: 1.0138x; 1.0015x over previous
#include <cuda_runtime.h>

// MedianPool2d 3x3, stride 1, reflect pad (1,1,1,1)
// float32 [16, 3, 512, 512] -> same shape.
//
// 4(W) x 2(H) outputs per thread. Vertical stage on FMA pipe via packed f32x2
// arithmetic compare-exchange; horizontal combine scalar FMNMX (ALU pipe).
// R7: halo columns come from neighbor lanes via SHFL instead of scalar LDGs
// (which cost 4 L1 wavefronts each). Only lane 0 / lane 31 issue a predicated
// 1-lane LDG; global reflect edges reuse in-register values (wl=1 -> q.y,
// wr=W-2 -> q.z). Cuts L1 wavefronts ~2x.

#define W 512
#define H 512

typedef unsigned long long u64;
typedef unsigned int u32;

__device__ __forceinline__ u64 pk(float x, float y) {
    u64 r; asm("mov.b64 %0, {%1, %2};" : "=l"(r) : "f"(x), "f"(y)); return r;
}
__device__ __forceinline__ float2 upk(u64 v) {
    float2 f; asm("mov.b64 {%0, %1}, %2;" : "=f"(f.x), "=f"(f.y) : "l"(v)); return f;
}

// packed compare-exchange on 2 fp32 lanes: lo=min, hi=max
__device__ __forceinline__ void cex2(u64 a, u64 b, u64& lo, u64& hi) {
    const u64 n1 = 0xBF800000BF800000ULL;
    const u64 hf = 0x3F0000003F000000ULL;
    const u64 nh = 0xBF000000BF000000ULL;
    u64 s, d, k, h;
    asm("add.rn.f32x2 %0, %1, %2;" : "=l"(s) : "l"(a), "l"(b));
    asm("fma.rn.f32x2 %0, %1, %2, %3;" : "=l"(d) : "l"(b), "l"(n1), "l"(a)); // a-b
    k = d & 0x7FFFFFFF7FFFFFFFULL;                                           // |a-b|
    asm("mul.rn.f32x2 %0, %1, %2;" : "=l"(h) : "l"(s), "l"(hf));             // 0.5(a+b)
    asm("fma.rn.f32x2 %0, %1, %2, %3;" : "=l"(lo) : "l"(k), "l"(nh), "l"(h));
    asm("fma.rn.f32x2 %0, %1, %2, %3;" : "=l"(hi) : "l"(k), "l"(hf), "l"(h));
}

__device__ __forceinline__ float med3(float a, float b, float c) {
    return fmaxf(fminf(a, b), fminf(fmaxf(a, b), c));
}

struct Row3 { u64 a, b, c; };   // packed columns (1,2) (3,4) (0,5)

__device__ __forceinline__ void emit_row(const Row3& pl, const Row3& ph,
                                         const Row3& t,
                                         float* __restrict__ dst) {
    float4 res;
    u64 loa, mia, hia, loc, mic, hic, tm;
    cex2(pl.a, t.a, loa, tm);
    cex2(ph.a, tm, mia, hia);
    cex2(pl.c, t.c, loc, tm);
    cex2(ph.c, tm, mic, hic);

    float2 la = upk(loa), lc = upk(loc);
    float2 ma = upk(mia), mc = upk(mic);
    float2 ha = upk(hia), hc = upk(hic);

    float sA  = fmaxf(la.x, la.y);
    float tA  = fminf(ha.x, ha.y);
    float q0A = fminf(ma.x, ma.y), q1A = fmaxf(ma.x, ma.y);

    u64 lob, mib, hib;
    cex2(pl.b, t.b, lob, tm);
    cex2(ph.b, tm, mib, hib);
    float2 lb = upk(lob), mb = upk(mib), hb = upk(hib);

    res.x = med3(fmaxf(lc.x, sA),
                 fmaxf(q0A, fminf(q1A, mc.x)),
                 fminf(hc.x, tA));
    res.y = med3(fmaxf(sA, lb.x),
                 fmaxf(q0A, fminf(q1A, mb.x)),
                 fminf(tA, hb.x));

    float sB  = fmaxf(lb.x, lb.y);
    float tB  = fminf(hb.x, hb.y);
    float q0B = fminf(mb.x, mb.y), q1B = fmaxf(mb.x, mb.y);

    res.z = med3(fmaxf(la.y, sB),
                 fmaxf(q0B, fminf(q1B, ma.y)),
                 fminf(ha.y, tB));
    res.w = med3(fmaxf(sB, lc.y),
                 fmaxf(q0B, fminf(q1B, mc.y)),
                 fminf(tB, hc.y));

    *reinterpret_cast<float4*>(dst) = res;
}

__global__ __launch_bounds__(128, 12)
void median3x3_kernel(const float* __restrict__ x, float* __restrict__ out) {
    const int tid   = threadIdx.x;        // 0..127
    const int lane  = tid & 31;
    const int h0    = blockIdx.x << 1;    // 2 output rows per block
    const u32 plane = blockIdx.y;         // 0..47
    const int w0    = tid << 2;

    const u32 base = plane * (u32)(H * W);

    // frame rows f0..f3 = input rows h0-1 .. h0+2 (reflected at edges)
    const int hr0 = (h0 == 0)     ? 1     : h0 - 1;
    const int hr3 = (h0 + 2 >= H) ? H - 2 : h0 + 2;

    const u32 o0 = base + (u32)hr0 * W;
    const u32 o1 = base + (u32)h0  * W;
    const u32 o2 = o1 + W;
    const u32 o3 = base + (u32)hr3 * W;

    // vector loads up front (4 LDG.128 in flight)
    float4 q0 = *reinterpret_cast<const float4*>(x + o0 + w0);
    float4 q1 = *reinterpret_cast<const float4*>(x + o1 + w0);
    float4 q2 = *reinterpret_cast<const float4*>(x + o2 + w0);
    float4 q3 = *reinterpret_cast<const float4*>(x + o3 + w0);

    // halo exchange via shuffle; boundary lanes fix up with predicated LDG.
    // left halo (w0-1): lane-1's q.w ; global edge (w0==0): reflect -> q.y
    // right halo (w0+4): lane+1's q.x ; global edge (w0+4==W): reflect -> q.z
    float l0 = __shfl_up_sync(0xffffffffu, q0.w, 1);
    float l1 = __shfl_up_sync(0xffffffffu, q1.w, 1);
    float l2 = __shfl_up_sync(0xffffffffu, q2.w, 1);
    float l3 = __shfl_up_sync(0xffffffffu, q3.w, 1);
    float e0 = __shfl_down_sync(0xffffffffu, q0.x, 1);
    float e1 = __shfl_down_sync(0xffffffffu, q1.x, 1);
    float e2 = __shfl_down_sync(0xffffffffu, q2.x, 1);
    float e3 = __shfl_down_sync(0xffffffffu, q3.x, 1);

    if (lane == 0) {
        if (w0 == 0) {
            l0 = q0.y; l1 = q1.y; l2 = q2.y; l3 = q3.y;     // reflect: wl = 1
        } else {
            l0 = x[o0 + w0 - 1]; l1 = x[o1 + w0 - 1];
            l2 = x[o2 + w0 - 1]; l3 = x[o3 + w0 - 1];
        }
    }
    if (lane == 31) {
        if (w0 + 4 == W) {
            e0 = q0.z; e1 = q1.z; e2 = q2.z; e3 = q3.z;     // reflect: wr = W-2
        } else {
            e0 = x[o0 + w0 + 4]; e1 = x[o1 + w0 + 4];
            e2 = x[o2 + w0 + 4]; e3 = x[o3 + w0 + 4];
        }
    }

    Row3 f0, f1, f2, f3;
    f0.a = pk(q0.x, q0.y); f0.b = pk(q0.z, q0.w); f0.c = pk(l0, e0);
    f1.a = pk(q1.x, q1.y); f1.b = pk(q1.z, q1.w); f1.c = pk(l1, e1);
    f2.a = pk(q2.x, q2.y); f2.b = pk(q2.z, q2.w); f2.c = pk(l2, e2);
    f3.a = pk(q3.x, q3.y); f3.b = pk(q3.z, q3.w); f3.c = pk(l3, e3);

    // pair sort rows f1,f2 (both die afterward)
    Row3 pl, ph;
    cex2(f1.a, f2.a, pl.a, ph.a);
    cex2(f1.b, f2.b, pl.b, ph.b);
    cex2(f1.c, f2.c, pl.c, ph.c);

    float* o = out + o1 + w0;
    emit_row(pl, ph, f0, o);        // output row h0
    emit_row(pl, ph, f3, o + W);    // output row h0+1
}

extern "C" void kernel_launch(void* const* d_in, const int* in_sizes, int n_in,
                              void* d_out, int out_size) {
    const float* x = (const float*)d_in[0];
    float* out = (float*)d_out;
    dim3 grid(H / 2, 48);    // 256 row-pairs x 48 planes
    dim3 block(128);
    median3x3_kernel<<<grid, block>>>(x, out);
}